// round 16
// baseline (speedup 1.0000x reference)
#include <cuda_runtime.h>
#include <cuda_fp16.h>
#include <math.h>

typedef unsigned long long ull;

#define NMAX 524288

// ---------------- device-global scratch ----------------
__device__ __align__(16) float g_T[92 * NMAX];     // ifrd transposed: [feat][pt]

// ---------------- weight layout in g_wt ----------------
// Stage-1 (trunk) offsets inside smem overlay:
#define A_GLOB_WT 0       // [57][32]
#define A_GLOB_B  1824
#define A_AGGW    1856
#define A_FC_WT   1888    // [32][16]
#define A_FC_B    2400
#define A_LR0_WT  2416    // [24][64]
#define A_LR0_B   3952
#define A_SIGMA_W 4016
#define A_VIEW_WT 4080    // [4][19]
#define A_VIEW_B  4156
#define A_SC      4176    // aggw_b, sigma_b
#define A_TOTAL   4180
// Stage-2 (col1/col2) offsets inside smem overlay:
#define B_C1WT    0       // [111][64]
#define B_C1B     7104
#define B_C2W     7168
#define B_C2B     7232
#define B_TOTAL   7236
#define GB_BASE   4608
#define GWT_TOTAL (GB_BASE + B_TOTAL)

__device__ __align__(16) float g_wt[GWT_TOTAL];

// dyn smem layout in half2 units (each slot indexed [..][t], thread-private):
// X region: point p at p*4096 + kk*128 + t   (kk = j/2, 32 kk)
// V region: point p at 8192 + p*1536 + kk*128 + t  (kk = k/2, 12 kk)
#define H2_X(p)  ((p) * 4096)
#define H2_V(p)  (8192 + (p) * 1536)
#define DYN_BYTES 45056

// ---------------- packed f32x2 helpers ----------------
__device__ __forceinline__ ull ffma2(ull a, ull b, ull c) {
    ull d; asm("fma.rn.f32x2 %0, %1, %2, %3;" : "=l"(d) : "l"(a), "l"(b), "l"(c));
    return d;
}
__device__ __forceinline__ ull fmul2(ull a, ull b) {
    ull d; asm("mul.rn.f32x2 %0, %1, %2;" : "=l"(d) : "l"(a), "l"(b));
    return d;
}
__device__ __forceinline__ ull pack2(float x) {
    ull r; asm("mov.b64 %0, {%1, %1};" : "=l"(r) : "r"(__float_as_uint(x)));
    return r;
}
__device__ __forceinline__ ull pack2f(float a, float b) {
    ull r; asm("mov.b64 %0, {%1, %2};" : "=l"(r)
               : "r"(__float_as_uint(a)), "r"(__float_as_uint(b)));
    return r;
}
__device__ __forceinline__ float2 unpack2(ull v) {
    unsigned lo, hi; asm("mov.b64 {%0, %1}, %2;" : "=r"(lo), "=r"(hi) : "l"(v));
    return make_float2(__uint_as_float(lo), __uint_as_float(hi));
}
__device__ __forceinline__ ull relu2(ull v) {
    float2 f = unpack2(v);
    return pack2f(fmaxf(f.x, 0.0f), fmaxf(f.y, 0.0f));
}
__device__ __forceinline__ float halfOf(ull v, int hi) {
    float2 f = unpack2(v);
    return hi ? f.y : f.x;
}

// 32-j accumulator (16 ull), j-packed
#define ACC16(acc, xx, woff)                                                     \
    {                                                                            \
        const ulonglong2* w2 = reinterpret_cast<const ulonglong2*>(sw + (woff)); \
        _Pragma("unroll")                                                        \
        for (int q = 0; q < 8; q++) {                                            \
            ulonglong2 ww = w2[q];                                               \
            acc[2 * q]     = ffma2(ww.x, (xx), acc[2 * q]);                      \
            acc[2 * q + 1] = ffma2(ww.y, (xx), acc[2 * q + 1]);                  \
        }                                                                        \
    }
// 16-j accumulator (8 ull)
#define ACC8(acc, xx, woff)                                                      \
    {                                                                            \
        const ulonglong2* w2 = reinterpret_cast<const ulonglong2*>(sw + (woff)); \
        _Pragma("unroll")                                                        \
        for (int q = 0; q < 4; q++) {                                            \
            ulonglong2 ww = w2[q];                                               \
            acc[2 * q]     = ffma2(ww.x, (xx), acc[2 * q]);                      \
            acc[2 * q + 1] = ffma2(ww.y, (xx), acc[2 * q + 1]);                  \
        }                                                                        \
    }
#define LOADB16(acc, off)                                                        \
    {                                                                            \
        const ulonglong2* b2 = reinterpret_cast<const ulonglong2*>(sw + (off));  \
        _Pragma("unroll")                                                        \
        for (int q = 0; q < 8; q++) {                                            \
            ulonglong2 bb = b2[q];                                               \
            acc[2 * q] = bb.x; acc[2 * q + 1] = bb.y;                            \
        }                                                                        \
    }
#define LOADB8(acc, off)                                                         \
    {                                                                            \
        const ulonglong2* b2 = reinterpret_cast<const ulonglong2*>(sw + (off));  \
        _Pragma("unroll")                                                        \
        for (int q = 0; q < 4; q++) {                                            \
            ulonglong2 bb = b2[q];                                               \
            acc[2 * q] = bb.x; acc[2 * q + 1] = bb.y;                            \
        }                                                                        \
    }

// ---------------- prep body (runs inside transpose kernel, block (0,0)) -------
__device__ void prep_body(int t, int bs,
                          const float* view_w, const float* view_b,
                          const float* glob_w, const float* glob_b,
                          const float* aggw_w, const float* aggw_b,
                          const float* fc_w,   const float* fc_b,
                          const float* lr0_w,  const float* lr0_b,
                          const float* sigma_w,const float* sigma_b,
                          const float* col1_w, const float* col1_b,
                          const float* col2_w, const float* col2_b) {
    for (int idx = t; idx < 32 * 57; idx += bs) {
        int j = idx / 57, k = idx % 57;
        g_wt[A_GLOB_WT + k * 32 + j] = glob_w[idx];
    }
    for (int idx = t; idx < 32; idx += bs) {
        g_wt[A_GLOB_B + idx] = glob_b[idx];
        g_wt[A_AGGW + idx]   = aggw_w[idx];
    }
    for (int idx = t; idx < 16 * 32; idx += bs) {
        int j = idx / 32, k = idx % 32;
        g_wt[A_FC_WT + k * 16 + j] = fc_w[idx];
    }
    for (int idx = t; idx < 16; idx += bs) g_wt[A_FC_B + idx] = fc_b[idx];
    for (int idx = t; idx < 64 * 24; idx += bs) {
        int j = idx / 24, k = idx % 24;
        g_wt[A_LR0_WT + k * 64 + j] = lr0_w[idx];
    }
    for (int idx = t; idx < 64; idx += bs) {
        g_wt[A_LR0_B + idx]   = lr0_b[idx];
        g_wt[A_SIGMA_W + idx] = sigma_w[idx];
        g_wt[GB_BASE + B_C1B + idx] = col1_b[idx];
        g_wt[GB_BASE + B_C2W + idx] = col2_w[idx];
    }
    for (int idx = t; idx < 64 * 111; idx += bs) {
        int j = idx / 111, k = idx % 111;
        g_wt[GB_BASE + B_C1WT + k * 64 + j] = col1_w[idx];
    }
    for (int idx = t; idx < 76; idx += bs) {
        int j = idx / 4, k = idx % 4;
        g_wt[A_VIEW_WT + k * 19 + j] = view_w[idx];
    }
    for (int idx = t; idx < 19; idx += bs) g_wt[A_VIEW_B + idx] = view_b[idx];
    if (t == 0) {
        g_wt[A_SC + 0] = aggw_b[0];
        g_wt[A_SC + 1] = sigma_b[0];
        g_wt[GB_BASE + B_C2B] = col2_b[0];
    }
}

// ---------------- transpose (+ prep in block (0,0)) ----------------
__global__ void transpose_prep_kernel(const float* __restrict__ in, float* __restrict__ outp,
                                      int rows, int cols,
                                      const float* view_w, const float* view_b,
                                      const float* glob_w, const float* glob_b,
                                      const float* aggw_w, const float* aggw_b,
                                      const float* fc_w,   const float* fc_b,
                                      const float* lr0_w,  const float* lr0_b,
                                      const float* sigma_w,const float* sigma_b,
                                      const float* col1_w, const float* col1_b,
                                      const float* col2_w, const float* col2_b) {
    __shared__ float tile[32][33];
    const int c0 = blockIdx.y * 32;
    const long long r0 = (long long)blockIdx.x * 32;
    const int tx = threadIdx.x, ty = threadIdx.y;
#pragma unroll
    for (int i = 0; i < 32; i += 8) {
        long long r = r0 + ty + i;
        int c = c0 + tx;
        if (r < rows && c < cols) tile[ty + i][tx] = in[r * cols + c];
    }
    __syncthreads();
#pragma unroll
    for (int i = 0; i < 32; i += 8) {
        int c = c0 + ty + i;
        long long r = r0 + tx;
        if (r < rows && c < cols) outp[(size_t)c * rows + r] = tile[tx][ty + i];
    }
    if (blockIdx.x == 0 && blockIdx.y == 0) {
        prep_body(ty * 32 + tx, 256,
                  view_w, view_b, glob_w, glob_b, aggw_w, aggw_b,
                  fc_w, fc_b, lr0_w, lr0_b, sigma_w, sigma_b,
                  col1_w, col1_b, col2_w, col2_b);
    }
}

// ---------------- trunk for ONE point (phases A/B/fc/lr0/sigma) ----------------
// Writes x (fp16) and vif (fp16) into dyn smem regions for point slot p.
__device__ __forceinline__ float trunk_point(
    const float* sw, const float* __restrict__ vox, __half2* hb,
    size_t sN, int ptp, int t, int p) {

#define INS(f) __ldg(&g_T[(size_t)(f) * sN + (size_t)ptp])

    // dirs
    float dirs[4][4];
#pragma unroll
    for (int s = 0; s < 4; s++)
#pragma unroll
        for (int c = 0; c < 4; c++) dirs[s][c] = INS(s * 23 + 19 + c);

    // ---- Phase A: stats + gf_base in REGISTERS ----
    ull gfb[16];
    LOADB16(gfb, A_GLOB_B);
#pragma unroll 2
    for (int k = 0; k < 19; k++) {
        float wb = sw[A_VIEW_B + k];
        float w0 = sw[A_VIEW_WT + 0 * 19 + k];
        float w1 = sw[A_VIEW_WT + 1 * 19 + k];
        float w2 = sw[A_VIEW_WT + 2 * 19 + k];
        float w3 = sw[A_VIEW_WT + 3 * 19 + k];
        float ssum = 0.0f, ssq = 0.0f;
#pragma unroll
        for (int s = 0; s < 4; s++) {
            float a = wb + w0 * dirs[s][0] + w1 * dirs[s][1]
                        + w2 * dirs[s][2] + w3 * dirs[s][3];
            a = fmaxf(a, 0.0f);
            float f = INS(s * 23 + k) + a;
            ssum += f;
            ssq += f * f;
        }
        float m = ssum * 0.25f;
        float vr = (ssq - 4.0f * m * m) * (1.0f / 3.0f);
        ull xv = pack2(vr);
        ACC16(gfb, xv, A_GLOB_WT + (19 + k) * 32);
        xv = pack2(m);
        ACC16(gfb, xv, A_GLOB_WT + (38 + k) * 32);
    }

    // ---- Phase B: per-view glob + online softmax agg ----
    ull num[16];
#pragma unroll
    for (int q = 0; q < 16; q++) num[q] = 0ull;
    float dsum = 0.0f, mmax = -1e30f;
    const float aggb = sw[A_SC + 0];

#pragma unroll
    for (int s = 0; s < 4; s++) {
        ull gf[16];
#pragma unroll
        for (int q = 0; q < 16; q++) gf[q] = gfb[q];
#pragma unroll 2
        for (int k = 0; k < 19; k++) {
            float a = sw[A_VIEW_B + k]
                    + sw[A_VIEW_WT + 0 * 19 + k] * dirs[s][0]
                    + sw[A_VIEW_WT + 1 * 19 + k] * dirs[s][1]
                    + sw[A_VIEW_WT + 2 * 19 + k] * dirs[s][2]
                    + sw[A_VIEW_WT + 3 * 19 + k] * dirs[s][3];
            a = fmaxf(a, 0.0f);
            float f = INS(s * 23 + k) + a;
            ull xk = pack2(f);
            ACC16(gf, xk, A_GLOB_WT + k * 32);
        }
        ull la = 0ull;
        {
            const ulonglong2* aw = reinterpret_cast<const ulonglong2*>(sw + A_AGGW);
#pragma unroll
            for (int q2 = 0; q2 < 8; q2++) {
                ulonglong2 a2 = aw[q2];
                gf[2 * q2]     = relu2(gf[2 * q2]);
                gf[2 * q2 + 1] = relu2(gf[2 * q2 + 1]);
                la = ffma2(a2.x, gf[2 * q2], la);
                la = ffma2(a2.y, gf[2 * q2 + 1], la);
            }
        }
        float2 lf = unpack2(la);
        float l = fmaxf(lf.x + lf.y + aggb, 0.0f);

        if (l > mmax) {
            float c = __expf(mmax - l); ull c2 = pack2(c);
            dsum *= c;
#pragma unroll
            for (int q = 0; q < 16; q++) num[q] = fmul2(num[q], c2);
            mmax = l;
        }
        float e = __expf(l - mmax); dsum += e; ull e2 = pack2(e);
#pragma unroll
        for (int q = 0; q < 16; q++) num[q] = ffma2(gf[q], e2, num[q]);
    }

    // ---- fc: 32 -> 16, build vif[24], store vif fp16 ----
    float vif[24];
    {
        float inv = 1.0f / dsum;
        ull fa[8];
        LOADB8(fa, A_FC_B);
#pragma unroll 4
        for (int k = 0; k < 32; k++) {
            ull xk = pack2(halfOf(num[k >> 1], k & 1) * inv);
            ACC8(fa, xk, A_FC_WT + k * 16);
        }
        const float4* vp4 = reinterpret_cast<const float4*>(vox + (size_t)ptp * 8);
        float4 va = __ldg(vp4), vb = __ldg(vp4 + 1);
        vif[0] = va.x; vif[1] = va.y; vif[2] = va.z; vif[3] = va.w;
        vif[4] = vb.x; vif[5] = vb.y; vif[6] = vb.z; vif[7] = vb.w;
#pragma unroll
        for (int j = 0; j < 16; j++)
            vif[8 + j] = fmaxf(halfOf(fa[j >> 1], j & 1), 0.0f);
#pragma unroll
        for (int kk = 0; kk < 12; kk++)
            hb[H2_V(p) + kk * 128 + t] = __floats2half2_rn(vif[2 * kk], vif[2 * kk + 1]);
    }

    // ---- lr0: 24 -> 64 (two 32-j tiles), relu, sigma dot, x -> fp16 smem ----
    ull siga = 0ull;
#pragma unroll
    for (int jt = 0; jt < 2; jt++) {
        const int j0 = jt * 32;
        ull xa[16];
        LOADB16(xa, A_LR0_B + j0);
#pragma unroll 4
        for (int k = 0; k < 24; k++) {
            ull xk = pack2(vif[k]);
            ACC16(xa, xk, A_LR0_WT + k * 64 + j0);
        }
        const ulonglong2* swg = reinterpret_cast<const ulonglong2*>(sw + A_SIGMA_W + j0);
#pragma unroll
        for (int q2 = 0; q2 < 8; q2++) {
            ulonglong2 w = swg[q2];
            ull ra = relu2(xa[2 * q2]);
            ull rb = relu2(xa[2 * q2 + 1]);
            siga = ffma2(w.x, ra, siga);
            siga = ffma2(w.y, rb, siga);
            int kk = (j0 + 4 * q2) >> 1;    // x pair index
            float2 fa = unpack2(ra), fb = unpack2(rb);
            hb[H2_X(p) + (kk + 0) * 128 + t] = __floats2half2_rn(fa.x, fa.y);
            hb[H2_X(p) + (kk + 1) * 128 + t] = __floats2half2_rn(fb.x, fb.y);
        }
    }
    float2 s2 = unpack2(siga);
    float l = s2.x + s2.y + sw[A_SC + 1];
    return (l > 20.0f) ? l : log1pf(expf(l));
#undef INS
}

// ---------------- main kernel ----------------
#define TB 128
#define PTSB 256   // points per block (P=2, adjacent pairs)

__global__ void __launch_bounds__(TB, 3)
nerf_main(const float* __restrict__ vox, float* __restrict__ out, int N) {
    extern __shared__ char dynsmem[];
    __half2* hb = (__half2*)dynsmem;               // x + vif fp16 spill (45KB)
    __shared__ __align__(16) float sov[B_TOTAL];   // weight overlay (28.9KB)
    const float* sw = sov;

    // stage-1 weights
    for (int idx = threadIdx.x; idx < A_TOTAL; idx += TB) sov[idx] = g_wt[idx];
    __syncthreads();

    const int t = threadIdx.x;
    const int base = blockIdx.x * PTSB;
    const int pt0 = base + 2 * t;       // even; pt1 = pt0 + 1
    const int pt1 = pt0 + 1;
    const bool vld = pt0 < N;           // N even
    const size_t pb = (size_t)(vld ? pt0 : 0);
    const size_t sN = (size_t)N;

    // ---- trunk, one point at a time (low register pressure, no spills) ----
    float sig0 = trunk_point(sw, vox, hb, sN, (int)pb,     t, 0);
    float sig1 = trunk_point(sw, vox, hb, sN, (int)pb + 1, t, 1);

    // ---- weight overlay swap: stage-2 (col1/col2) ----
    __syncthreads();
    for (int idx = threadIdx.x; idx < B_TOTAL; idx += TB) sov[idx] = g_wt[GB_BASE + idx];
    __syncthreads();

#define IN2(f) __ldg(reinterpret_cast<const ull*>(&g_T[(size_t)(f) * sN + pb]))

    // ---- col1: 4 x 16-j tiles + col2 partial logits (point-paired) ----
    ull lacc0[4], lacc1[4];
#pragma unroll
    for (int s = 0; s < 4; s++) { lacc0[s] = 0ull; lacc1[s] = 0ull; }

#pragma unroll 1
    for (int jt = 0; jt < 4; jt++) {
        const int j0 = jt * 16;
        ull ba0[8], ba1[8];
        LOADB8(ba0, B_C1B + j0);
#pragma unroll
        for (int q = 0; q < 8; q++) ba1[q] = ba0[q];

        // x rows (k = 0..63) from fp16 spill, 2 rows per kk
#pragma unroll 4
        for (int kk = 0; kk < 32; kk++) {
            float2 x0 = __half22float2(hb[H2_X(0) + kk * 128 + t]);
            float2 x1 = __half22float2(hb[H2_X(1) + kk * 128 + t]);
            ull xk;
            xk = pack2(x0.x); ACC8(ba0, xk, B_C1WT + (2 * kk) * 64 + j0);
            xk = pack2(x0.y); ACC8(ba0, xk, B_C1WT + (2 * kk + 1) * 64 + j0);
            xk = pack2(x1.x); ACC8(ba1, xk, B_C1WT + (2 * kk) * 64 + j0);
            xk = pack2(x1.y); ACC8(ba1, xk, B_C1WT + (2 * kk + 1) * 64 + j0);
        }
        // vif rows (k = 64..87) from fp16 spill
#pragma unroll 4
        for (int kk = 0; kk < 12; kk++) {
            float2 v0 = __half22float2(hb[H2_V(0) + kk * 128 + t]);
            float2 v1 = __half22float2(hb[H2_V(1) + kk * 128 + t]);
            ull xk;
            xk = pack2(v0.x); ACC8(ba0, xk, B_C1WT + (64 + 2 * kk) * 64 + j0);
            xk = pack2(v0.y); ACC8(ba0, xk, B_C1WT + (64 + 2 * kk + 1) * 64 + j0);
            xk = pack2(v1.x); ACC8(ba1, xk, B_C1WT + (64 + 2 * kk) * 64 + j0);
            xk = pack2(v1.y); ACC8(ba1, xk, B_C1WT + (64 + 2 * kk + 1) * 64 + j0);
        }
        // per-view rows (k = 88..110) + col2 partial dot
#pragma unroll
        for (int s = 0; s < 4; s++) {
            ull va0[8], va1[8];
#pragma unroll
            for (int q = 0; q < 8; q++) { va0[q] = ba0[q]; va1[q] = ba1[q]; }
#pragma unroll 4
            for (int k = 0; k < 23; k++) {
                float2 fv = unpack2(IN2(s * 23 + k));
                ull x0 = pack2(fv.x);
                ull x1 = pack2(fv.y);
                ACC8(va0, x0, B_C1WT + (88 + k) * 64 + j0);
                ACC8(va1, x1, B_C1WT + (88 + k) * 64 + j0);
            }
            const ulonglong2* cw =
                reinterpret_cast<const ulonglong2*>(sw + B_C2W + j0);
#pragma unroll
            for (int q2 = 0; q2 < 4; q2++) {
                ulonglong2 w = cw[q2];
                lacc0[s] = ffma2(w.x, relu2(va0[2 * q2]), lacc0[s]);
                lacc0[s] = ffma2(w.y, relu2(va0[2 * q2 + 1]), lacc0[s]);
                lacc1[s] = ffma2(w.x, relu2(va1[2 * q2]), lacc1[s]);
                lacc1[s] = ffma2(w.y, relu2(va1[2 * q2 + 1]), lacc1[s]);
            }
        }
    }

    // ---- color softmax + output ----
    const float col2b = sw[B_C2B];
    float l0[4], l1[4];
#pragma unroll
    for (int s = 0; s < 4; s++) {
        float2 a = unpack2(lacc0[s]);
        float2 b = unpack2(lacc1[s]);
        l0[s] = fmaxf(a.x + a.y + col2b, 0.0f);
        l1[s] = fmaxf(b.x + b.y + col2b, 0.0f);
    }
    float m0 = fmaxf(fmaxf(l0[0], l0[1]), fmaxf(l0[2], l0[3]));
    float m1 = fmaxf(fmaxf(l1[0], l1[1]), fmaxf(l1[2], l1[3]));
    float cn0[3] = {0, 0, 0}, cn1[3] = {0, 0, 0}, cd0 = 0.0f, cd1 = 0.0f;
#pragma unroll
    for (int s = 0; s < 4; s++) {
        float e0 = __expf(l0[s] - m0);
        float e1 = __expf(l1[s] - m1);
        cd0 += e0; cd1 += e1;
#pragma unroll
        for (int c = 0; c < 3; c++) {
            float2 rgb = unpack2(IN2(s * 23 + 16 + c));
            cn0[c] += rgb.x * e0;
            cn1[c] += rgb.y * e1;
        }
    }
    if (vld) {
        float inv0 = 1.0f / cd0;
        float inv1 = 1.0f / cd1;
        float4 o0 = make_float4(cn0[0] * inv0, cn0[1] * inv0, cn0[2] * inv0, sig0);
        float4 o1 = make_float4(cn1[0] * inv1, cn1[1] * inv1, cn1[2] * inv1, sig1);
        reinterpret_cast<float4*>(out)[pt0] = o0;
        reinterpret_cast<float4*>(out)[pt1] = o1;
    }
#undef IN2
}

extern "C" void kernel_launch(void* const* d_in, const int* in_sizes, int n_in,
                              void* d_out, int out_size) {
    const float* vox     = (const float*)d_in[0];
    const float* ifrd    = (const float*)d_in[1];
    const float* view_w  = (const float*)d_in[2];
    const float* view_b  = (const float*)d_in[3];
    const float* glob_w  = (const float*)d_in[4];
    const float* glob_b  = (const float*)d_in[5];
    const float* aggw_w  = (const float*)d_in[6];
    const float* aggw_b  = (const float*)d_in[7];
    const float* fc_w    = (const float*)d_in[8];
    const float* fc_b    = (const float*)d_in[9];
    const float* lr0_w   = (const float*)d_in[10];
    const float* lr0_b   = (const float*)d_in[11];
    const float* sigma_w = (const float*)d_in[12];
    const float* sigma_b = (const float*)d_in[13];
    const float* col1_w  = (const float*)d_in[14];
    const float* col1_b  = (const float*)d_in[15];
    const float* col2_w  = (const float*)d_in[16];
    const float* col2_b  = (const float*)d_in[17];
    float* out = (float*)d_out;

    int N = in_sizes[0] / 8;
    if (N > NMAX) N = NMAX;

    // static (28.9KB) + dynamic (45KB) exceeds 48KB default -> opt in.
    cudaFuncSetAttribute(nerf_main, cudaFuncAttributeMaxDynamicSharedMemorySize, DYN_BYTES);

    float* tptr = nullptr;
    cudaGetSymbolAddress((void**)&tptr, g_T);

    dim3 tb(32, 8);
    dim3 tg1((N + 31) / 32, (92 + 31) / 32);
    transpose_prep_kernel<<<tg1, tb>>>(ifrd, tptr, N, 92,
                                       view_w, view_b, glob_w, glob_b, aggw_w, aggw_b,
                                       fc_w, fc_b, lr0_w, lr0_b, sigma_w, sigma_b,
                                       col1_w, col1_b, col2_w, col2_b);

    int blocks = (N + PTSB - 1) / PTSB;
    nerf_main<<<blocks, TB, DYN_BYTES>>>(vox, out, N);
}